// round 9
// baseline (speedup 1.0000x reference)
#include <cuda_runtime.h>

// CostVolumeBidirectional: f1,f2 (8,96,96,320) f32 -> out (8,9,96,320) f32
// out[b][d][h][w] = (1/96) * sum_c f1[b][c][h][w] * f2[b][c][h][w-(d-4)]
// zero where w-(d-4) outside [0,320).
//
// R9: 2-cols-per-thread tile (18 accumulators instead of 36) to cut register
// pressure (64 -> ~44 regs) and double thread count: 491,520 threads,
// 5 blocks/SM = 40 warps/SM. Attacks the occupancy cap identified in R8
// (regs=64 bound us to 32 warps; DRAM stuck at 53%).

#define BS 8
#define FS 96
#define H  96
#define W  320
#define WG (W / 2)      // 160 float2 groups per row
#define NP 9            // disparity planes

#define GROUPS 64       // float2-groups per block
#define CHUNKS 4        // channel chunks per group
#define CHP (FS / CHUNKS)  // 24 channels per thread

__global__ __launch_bounds__(256, 5)
void cost_volume_kernel(const float* __restrict__ f1,
                        const float* __restrict__ f2,
                        float* __restrict__ out) {
    // partial accumulators: [chunk][group][plane] as float2 (2 columns)
    __shared__ float2 s[CHUNKS][GROUPS][NP];   // 18 KB

    const int tid = threadIdx.x;
    const int g   = tid & (GROUPS - 1);
    const int cc  = tid >> 6;

    const int t  = blockIdx.x * GROUPS + g;    // global float2-group id
    const int wg = t % WG;                     // column pair index (cols 2*wg, 2*wg+1)
    const int bh = t / WG;
    const int h  = bh % H;
    const int b  = bh / H;

    float acc[NP][2];
#pragma unroll
    for (int d = 0; d < NP; d++) {
        acc[d][0] = 0.0f;
        acc[d][1] = 0.0f;
    }

    const int cs = H * W;
    const size_t base = ((size_t)b * FS + cc * CHP) * cs + (size_t)h * W + (size_t)wg * 2;
    const float* p1 = f1 + base;
    const float* p2 = f2 + base;

    // f2 window float2s at column offsets -4,-2,0,+2,+4 relative to 2*wg.
    const bool v0 = (wg >= 2);        // cols 2wg-4,2wg-3
    const bool v1 = (wg >= 1);        // cols 2wg-2,2wg-1
    const bool v3 = (wg <= WG - 2);   // cols 2wg+2,2wg+3
    const bool v4 = (wg <= WG - 3);   // cols 2wg+4,2wg+5
    const float2 z2 = make_float2(0.f, 0.f);

#pragma unroll 4
    for (int c = 0; c < CHP; c++) {
        const float* q1 = p1 + (size_t)c * cs;
        const float* q2 = p2 + (size_t)c * cs;

        float2 a  = *(const float2*)(q1);
        float2 w0 = v0 ? *(const float2*)(q2 - 4) : z2;
        float2 w1 = v1 ? *(const float2*)(q2 - 2) : z2;
        float2 w2 = *(const float2*)(q2);
        float2 w3 = v3 ? *(const float2*)(q2 + 2) : z2;
        float2 w4 = v4 ? *(const float2*)(q2 + 4) : z2;

        // wf[m] = f2 column (2wg - 4 + m), m in [0,10)
        float wf[10] = {w0.x, w0.y, w1.x, w1.y, w2.x,
                        w2.y, w3.x, w3.y, w4.x, w4.y};

        // plane d => shift i = d-4; col 2wg needs wf[8-d], col 2wg+1 needs wf[9-d]
#pragma unroll
        for (int d = 0; d < NP; d++) {
            acc[d][0] = fmaf(a.x, wf[8 - d], acc[d][0]);
            acc[d][1] = fmaf(a.y, wf[9 - d], acc[d][1]);
        }
    }

#pragma unroll
    for (int d = 0; d < NP; d++) {
        s[cc][g][d] = make_float2(acc[d][0], acc[d][1]);
    }
    __syncthreads();

    // reduce 4 chunks + write out: 64 groups x 9 planes = 576 float2 stores
    const float inv = 1.0f / (float)FS;
    for (int item = tid; item < GROUPS * NP; item += 256) {
        const int g2 = item / NP;
        const int d  = item % NP;

        float2 a0 = s[0][g2][d];
        float2 a1 = s[1][g2][d];
        float2 a2 = s[2][g2][d];
        float2 a3 = s[3][g2][d];

        float2 o;
        o.x = (a0.x + a1.x + a2.x + a3.x) * inv;
        o.y = (a0.y + a1.y + a2.y + a3.y) * inv;

        const int t2  = blockIdx.x * GROUPS + g2;
        const int wg2 = t2 % WG;
        const int bh2 = t2 / WG;
        const int h2  = bh2 % H;
        const int b2  = bh2 / H;

        const size_t oidx = (((size_t)b2 * NP + d) * H + h2) * W + (size_t)wg2 * 2;
        *(float2*)(out + oidx) = o;
    }
}

extern "C" void kernel_launch(void* const* d_in, const int* in_sizes, int n_in,
                              void* d_out, int out_size) {
    const float* f1 = (const float*)d_in[0];
    const float* f2 = (const float*)d_in[1];
    float* out = (float*)d_out;

    const int total_groups = BS * H * WG;          // 122880
    const int grid = total_groups / GROUPS;        // 1920 blocks
    cost_volume_kernel<<<grid, 256>>>(f1, f2, out);
}

// round 10
// speedup vs baseline: 1.4462x; 1.4462x over previous
#include <cuda_runtime.h>

// CostVolumeBidirectional: f1,f2 (8,96,96,320) f32 -> out (8,9,96,320) f32
// out[b][d][h][w] = (1/96) * sum_c f1[b][c][h][w] * f2[b][c][h][w-(d-4)]
// zero where w-(d-4) outside [0,320).
//
// R10: revert to the 4-col tile (R8 structure, best MLP/warp) but fix the
// wave-quantization waste: CHUNKS=2 (48 ch/thread), block=128 (64 groups x 2
// chunks), grid=960. Total 122,880 threads < 151,552 resident capacity at
// 8 blocks/SM (64 regs) -> SINGLE WAVE, no 1.62-wave tail that R8 paid.

#define BS 8
#define FS 96
#define H  96
#define W  320
#define WQ (W / 4)      // 80 float4 groups per row
#define NP 9            // disparity planes

#define GROUPS 64       // float4-groups per block
#define CHUNKS 2        // channel chunks per group
#define CHP (FS / CHUNKS)  // 48 channels per thread
#define BLOCK (GROUPS * CHUNKS)   // 128 threads

__global__ __launch_bounds__(BLOCK, 8)
void cost_volume_kernel(const float* __restrict__ f1,
                        const float* __restrict__ f2,
                        float* __restrict__ out) {
    // partial accumulators: [chunk][group][plane] as float4 (4 columns)
    __shared__ float4 s[CHUNKS][GROUPS][NP];   // 18 KB

    const int tid = threadIdx.x;
    const int g   = tid & (GROUPS - 1);
    const int cc  = tid >> 6;

    const int t  = blockIdx.x * GROUPS + g;    // global float4-group id
    const int wq = t % WQ;
    const int bh = t / WQ;
    const int h  = bh % H;
    const int b  = bh / H;

    float acc[NP][4];
#pragma unroll
    for (int d = 0; d < NP; d++)
#pragma unroll
        for (int k = 0; k < 4; k++) acc[d][k] = 0.0f;

    const int cs = H * W;
    const size_t base = ((size_t)b * FS + cc * CHP) * cs + (size_t)h * W + (size_t)wq * 4;
    const float* p1 = f1 + base;
    const float* p2 = f2 + base;

    const bool hasL = (wq > 0);
    const bool hasR = (wq < WQ - 1);
    const float4 z4 = make_float4(0.f, 0.f, 0.f, 0.f);

#pragma unroll 4
    for (int c = 0; c < CHP; c++) {
        const float* q1 = p1 + (size_t)c * cs;
        const float* q2 = p2 + (size_t)c * cs;

        float4 a = *(const float4*)(q1);
        float4 m = *(const float4*)(q2);
        float4 l = hasL ? *(const float4*)(q2 - 4) : z4;
        float4 r = hasR ? *(const float4*)(q2 + 4) : z4;

        float w12[12] = {l.x, l.y, l.z, l.w,
                         m.x, m.y, m.z, m.w,
                         r.x, r.y, r.z, r.w};
        float av[4] = {a.x, a.y, a.z, a.w};

        // plane d => shift i = d-4; f2 window index = k + 8 - d
#pragma unroll
        for (int d = 0; d < NP; d++) {
#pragma unroll
            for (int k = 0; k < 4; k++) {
                acc[d][k] = fmaf(av[k], w12[k + 8 - d], acc[d][k]);
            }
        }
    }

    // stash partials
#pragma unroll
    for (int d = 0; d < NP; d++) {
        s[cc][g][d] = make_float4(acc[d][0], acc[d][1], acc[d][2], acc[d][3]);
    }
    __syncthreads();

    // reduce 2 chunks + write out: 64 groups x 9 planes = 576 float4 stores
    const float inv = 1.0f / (float)FS;
    for (int item = tid; item < GROUPS * NP; item += BLOCK) {
        const int g2 = item / NP;
        const int d  = item % NP;

        float4 a0 = s[0][g2][d];
        float4 a1 = s[1][g2][d];

        float4 o;
        o.x = (a0.x + a1.x) * inv;
        o.y = (a0.y + a1.y) * inv;
        o.z = (a0.z + a1.z) * inv;
        o.w = (a0.w + a1.w) * inv;

        const int t2  = blockIdx.x * GROUPS + g2;
        const int wq2 = t2 % WQ;
        const int bh2 = t2 / WQ;
        const int h2  = bh2 % H;
        const int b2  = bh2 / H;

        const size_t oidx = (((size_t)b2 * NP + d) * H + h2) * W + (size_t)wq2 * 4;
        *(float4*)(out + oidx) = o;
    }
}

extern "C" void kernel_launch(void* const* d_in, const int* in_sizes, int n_in,
                              void* d_out, int out_size) {
    const float* f1 = (const float*)d_in[0];
    const float* f2 = (const float*)d_in[1];
    float* out = (float*)d_out;

    const int total_groups = BS * H * WQ;          // 61440
    const int grid = total_groups / GROUPS;        // 960 blocks
    cost_volume_kernel<<<grid, BLOCK>>>(f1, f2, out);
}